// round 2
// baseline (speedup 1.0000x reference)
#include <cuda_runtime.h>

// Problem constants
#define BB 2
#define NN 256
#define FF 64
#define HH 64
#define NHEADS 4
#define KK 50
#define CC 256   // HEADS*H

// ---------------- device scratch (no runtime alloc allowed) ----------------
__device__ float g_A [BB*NN*KK];   // h_j @ W_in[0:64]
__device__ float g_Bb[BB*NN*KK];   // h_i @ W_in[64:128]
__device__ float g_U [BB*NN*HH];   // h_j @ W_o1[0:64]
__device__ float g_Wp[BB*NN*HH];   // h_i @ W_o1[64:128]

// ---------------- helpers ----------------
__device__ __forceinline__ float siluf(float a) {
    return a * __fdividef(1.f, 1.f + __expf(-a));
}
__device__ __forceinline__ float sigmoidf_(float a) {
    return __fdividef(1.f, 1.f + __expf(-a));
}
__device__ __forceinline__ float fast_tanhf(float x) {
    float ax = fabsf(x);
    float e  = __expf(-2.f * ax);
    float t  = __fdividef(1.f - e, 1.f + e);
    return copysignf(t, x);
}

// packed f32x2 fma (ptxas never emits this from C++; inline PTX, sm_100+)
__device__ __forceinline__ void fma2(unsigned long long& acc,
                                     unsigned long long a,
                                     unsigned long long b) {
    asm("fma.rn.f32x2 %0, %1, %2, %0;" : "+l"(acc) : "l"(a), "l"(b));
}
__device__ __forceinline__ unsigned long long bcast2(float w) {
    unsigned long long r;
    asm("mov.b64 %0, {%1, %1};" : "=l"(r) : "f"(w));
    return r;
}
__device__ __forceinline__ void unpack2(unsigned long long v, float& x, float& y) {
    asm("mov.b64 {%0, %1}, %2;" : "=f"(x), "=f"(y) : "l"(v));
}

// block reduce of 4 floats (8 warps / 256 threads). red: >= 36 floats, 16B aligned.
template<int DO_MAX>
__device__ __forceinline__ float4 block_red4(float4 v, int tid, float* red) {
    #pragma unroll
    for (int o = 16; o > 0; o >>= 1) {
        float ax = __shfl_xor_sync(0xffffffffu, v.x, o);
        float ay = __shfl_xor_sync(0xffffffffu, v.y, o);
        float az = __shfl_xor_sync(0xffffffffu, v.z, o);
        float aw = __shfl_xor_sync(0xffffffffu, v.w, o);
        if (DO_MAX) { v.x = fmaxf(v.x, ax); v.y = fmaxf(v.y, ay); v.z = fmaxf(v.z, az); v.w = fmaxf(v.w, aw); }
        else        { v.x += ax; v.y += ay; v.z += az; v.w += aw; }
    }
    if ((tid & 31) == 0) ((float4*)red)[tid >> 5] = v;
    __syncthreads();
    if (tid < 32) {
        float4 r;
        if (tid < 8) r = ((float4*)red)[tid];
        else {
            float id = DO_MAX ? __int_as_float(0xff800000) : 0.f;
            r = make_float4(id, id, id, id);
        }
        #pragma unroll
        for (int o = 4; o > 0; o >>= 1) {
            float ax = __shfl_xor_sync(0xffffffffu, r.x, o);
            float ay = __shfl_xor_sync(0xffffffffu, r.y, o);
            float az = __shfl_xor_sync(0xffffffffu, r.z, o);
            float aw = __shfl_xor_sync(0xffffffffu, r.w, o);
            if (DO_MAX) { r.x = fmaxf(r.x, ax); r.y = fmaxf(r.y, ay); r.z = fmaxf(r.z, az); r.w = fmaxf(r.w, aw); }
            else        { r.x += ax; r.y += ay; r.z += az; r.w += aw; }
        }
        if (tid == 0) ((float4*)red)[8] = r;
    }
    __syncthreads();
    float4 out = ((float4*)red)[8];
    __syncthreads();
    return out;
}

// ---------------- K0: per-node precompute ----------------
__global__ void prenode_kernel(const float* __restrict__ h,
                               const float* __restrict__ W_in,
                               const float* __restrict__ W_o1) {
    __shared__ float hs[FF];
    int node = blockIdx.x;
    int t = threadIdx.x;
    if (t < FF) hs[t] = h[node * FF + t];
    __syncthreads();
    if (t < KK) {
        float a = 0.f, bv = 0.f;
        #pragma unroll
        for (int f = 0; f < FF; f++) {
            float hv = hs[f];
            a  += hv * W_in[f * KK + t];
            bv += hv * W_in[(FF + f) * KK + t];
        }
        g_A [node * KK + t] = a;
        g_Bb[node * KK + t] = bv;
    } else if (t >= 64 && t < 128) {
        int c = t - 64;
        float u = 0.f, w = 0.f;
        #pragma unroll
        for (int f = 0; f < FF; f++) {
            float hv = hs[f];
            u += hv * W_o1[f * HH + c];
            w += hv * W_o1[(FF + f) * HH + c];
        }
        g_U [node * HH + c] = u;
        g_Wp[node * HH + c] = w;
    }
}

// ---------------- shared memory layout (offsets in floats) ----------------
#define O_HE     0                     // 256*65 = 16640
#define O_ATT    16640                 // 1024
#define O_XDN    17664                 // 1024 (float4 per j: xd.xyz, norm)
#define O_HET    18688                 // 5120 (256 rows * stride 20)
// aliases over O_HET after phase 4:
#define O_CN     18688                 // 256
#define O_P1     18944                 // 64
#define O_HCOMB  19008                 // 64
#define O_N1     19072                 // 64
#define O_HN     19136                 // 64
#define O_HESUM  23808                 // 256
#define O_HI     24064                 // 64
#define O_WIB    24128                 // 64
#define O_WON    24192                 // 64
#define O_BO2    24256                 // 64
#define O_BI     24320                 // 64 (50 used)
#define O_MEAN   24384                 // 64
#define O_BETA   24448                 // 64
#define O_WS     24512                 // 256
#define O_BSG    24768                 // 8 (bs[4], gamma[4])
#define O_XI     24776                 // 4
#define O_RED    24784                 // 36 -> pad to 24832
#define O_UNION  24832
#define O_AS     (O_UNION)             // 256*51 = 13056
#define O_WO1K   (O_UNION + 13056)     // 3200
#define O_WO2    (O_UNION + 16256)     // 4096
#define O_WXLO   (O_UNION)             // 128*256 = 32768 (phase 4)
#define SMEM_FLOATS (O_UNION + 32768)  // 57600
#define SMEM_BYTES  (SMEM_FLOATS * 4)  // 230400

// ---------------- K1: fused per-(b,i) kernel ----------------
__global__ __launch_bounds__(256, 1)
void sake_kernel(const float* __restrict__ h, const float* __restrict__ x,
                 const float* __restrict__ v,
                 const float* __restrict__ means, const float* __restrict__ betas,
                 const float* __restrict__ b_in,
                 const float* __restrict__ W_o1, const float* __restrict__ b_o1,
                 const float* __restrict__ W_o2, const float* __restrict__ b_o2,
                 const float* __restrict__ Ws,  const float* __restrict__ bs,
                 const float* __restrict__ log_gamma,
                 const float* __restrict__ Wx,
                 const float* __restrict__ Wp1, const float* __restrict__ bp1,
                 const float* __restrict__ Wp2, const float* __restrict__ bp2,
                 const float* __restrict__ Wn1, const float* __restrict__ bn1,
                 const float* __restrict__ Wn2, const float* __restrict__ bn2,
                 const float* __restrict__ Wv_mix,
                 const float* __restrict__ Wvel1, const float* __restrict__ bvel1,
                 const float* __restrict__ Wvel2,
                 float* __restrict__ outH, float* __restrict__ outX,
                 float* __restrict__ outV) {
    extern __shared__ float sm[];
    const int tid  = threadIdx.x;
    const int bid  = blockIdx.x;     // = node index b*256 + i
    const int b    = bid >> 8;
    const int i    = bid & 255;
    const int nodeI = bid;

    float* he    = sm + O_HE;     // [256][65]
    float* att_s = sm + O_ATT;    // [256][4]
    float* xdn   = sm + O_XDN;    // [256][4]
    float* heT   = sm + O_HET;    // [256][20]
    float* he_e  = sm + O_HESUM;  // [256]
    float* hi_s  = sm + O_HI;
    float* wib   = sm + O_WIB;
    float* won   = sm + O_WON;
    float* bo2_s = sm + O_BO2;
    float* bi_s  = sm + O_BI;
    float* mn_s  = sm + O_MEAN;
    float* bt_s  = sm + O_BETA;
    float* ws_s  = sm + O_WS;
    float* bsg   = sm + O_BSG;
    float* xi_s  = sm + O_XI;
    float* red   = sm + O_RED;
    float* As    = sm + O_AS;     // [256][51]
    float* wo1k  = sm + O_WO1K;   // [50][64]
    float* wo2   = sm + O_WO2;    // [64][64]
    float* wxlo  = sm + O_WXLO;   // [128][256]

    // ---- preload ----
    if (tid < FF) {
        hi_s[tid]  = h[nodeI * FF + tid];
        wib[tid]   = g_Wp[nodeI * HH + tid] + b_o1[tid];
        won[tid]   = W_o1[178 * HH + tid];
        bo2_s[tid] = b_o2[tid];
    }
    if (tid < KK) {
        bi_s[tid] = g_Bb[nodeI * KK + tid] + b_in[tid];
        mn_s[tid] = means[tid];
        bt_s[tid] = betas[tid];
    }
    ws_s[tid] = Ws[tid];                 // 64x4 = 256
    if (tid < 4) {
        bsg[tid]     = bs[tid];
        bsg[4 + tid] = __expf(log_gamma[tid]);
        if (tid < 3) xi_s[tid] = x[nodeI * 3 + tid];
    }
    for (int idx = tid; idx < NN * KK; idx += 256) {
        int j = idx / KK, k = idx - j * KK;
        As[j * 51 + k] = g_A[b * NN * KK + idx];
    }
    for (int idx = tid; idx < NN * HH; idx += 256) {
        int j = idx >> 6, f = idx & 63;
        he[j * 65 + f] = g_U[b * NN * HH + idx];
    }
    for (int idx = tid; idx < KK * HH; idx += 256) wo1k[idx] = W_o1[128 * HH + idx];
    for (int idx = tid; idx < HH * HH; idx += 256) wo2[idx]  = W_o2[idx];
    __syncthreads();

    // ---- phase 1: edge model (thread = j) ----
    const int j = tid;
    float xjx = x[(b * NN + j) * 3 + 0];
    float xjy = x[(b * NN + j) * 3 + 1];
    float xjz = x[(b * NN + j) * 3 + 2];
    float dx = xjx - xi_s[0], dy = xjy - xi_s[1], dz = xjz - xi_s[2];
    float d2 = fmaxf(dx * dx + dy * dy + dz * dz, 0.f);
    float normv = sqrtf(d2 + 1e-5f);
    float rinv  = __fdividef(1.f, normv + 1e-5f);
    {
        float4 xv = make_float4(dx * rinv, dy * rinv, dz * rinv, normv);
        *(float4*)&xdn[j * 4] = xv;
    }
    float en = __expf(-normv);

    float acc[64];
    #pragma unroll
    for (int f = 0; f < 64; f++) acc[f] = he[j * 65 + f] + wib[f] + normv * won[f];

    for (int k = 0; k < KK; k++) {
        float hk = As[j * 51 + k] + bi_s[k];
        float df = en - mn_s[k];
        float s  = __expf(-bt_s[k] * df * df) * hk;
        const float* wr = &wo1k[k * 64];
        #pragma unroll
        for (int f = 0; f < 64; f++) acc[f] += s * wr[f];
    }
    #pragma unroll
    for (int f = 0; f < 64; f++) acc[f] = siluf(acc[f]);

    #pragma unroll
    for (int g = 0; g < 4; g++) {
        float o[16];
        #pragma unroll
        for (int q = 0; q < 16; q++) o[q] = bo2_s[g * 16 + q];
        for (int f = 0; f < 64; f++) {
            float a = acc[f];
            const float* wr = &wo2[f * 64 + g * 16];
            #pragma unroll
            for (int q = 0; q < 16; q++) o[q] += a * wr[q];
        }
        #pragma unroll
        for (int q = 0; q < 16; q++) he[j * 65 + g * 16 + q] = o[q];
    }

    // ---- phase 2: attentions (softmax over j) ----
    float z0 = bsg[0], z1 = bsg[1], z2 = bsg[2], z3 = bsg[3];
    for (int f = 0; f < 64; f++) {
        float a = he[j * 65 + f];
        z0 += a * ws_s[f * 4 + 0];
        z1 += a * ws_s[f * 4 + 1];
        z2 += a * ws_s[f * 4 + 2];
        z3 += a * ws_s[f * 4 + 3];
    }
    // celu(alpha=2)
    z0 = (z0 > 0.f) ? z0 : 2.f * (__expf(0.5f * z0) - 1.f);
    z1 = (z1 > 0.f) ? z1 : 2.f * (__expf(0.5f * z1) - 1.f);
    z2 = (z2 > 0.f) ? z2 : 2.f * (__expf(0.5f * z2) - 1.f);
    z3 = (z3 > 0.f) ? z3 : 2.f * (__expf(0.5f * z3) - 1.f);
    float diag = (j == i) ? 1e5f : 0.f;
    float4 el = make_float4(-(normv + diag) * bsg[4], -(normv + diag) * bsg[5],
                            -(normv + diag) * bsg[6], -(normv + diag) * bsg[7]);
    float4 sl = make_float4(z0 - diag, z1 - diag, z2 - diag, z3 - diag);

    float4 m  = block_red4<1>(el, tid, red);
    float4 ee = make_float4(__expf(el.x - m.x), __expf(el.y - m.y),
                            __expf(el.z - m.z), __expf(el.w - m.w));
    float4 s  = block_red4<0>(ee, tid, red);
    float4 eucl = make_float4(__fdividef(ee.x, s.x), __fdividef(ee.y, s.y),
                              __fdividef(ee.z, s.z), __fdividef(ee.w, s.w));

    m  = block_red4<1>(sl, tid, red);
    ee = make_float4(__expf(sl.x - m.x), __expf(sl.y - m.y),
                     __expf(sl.z - m.z), __expf(sl.w - m.w));
    s  = block_red4<0>(ee, tid, red);
    float4 sem = make_float4(__fdividef(ee.x, s.x), __fdividef(ee.y, s.y),
                             __fdividef(ee.z, s.z), __fdividef(ee.w, s.w));

    float4 q4 = make_float4(eucl.x * sem.x, eucl.y * sem.y, eucl.z * sem.z, eucl.w * sem.w);
    m  = block_red4<1>(q4, tid, red);
    ee = make_float4(__expf(q4.x - m.x), __expf(q4.y - m.y),
                     __expf(q4.z - m.z), __expf(q4.w - m.w));
    s  = block_red4<0>(ee, tid, red);
    att_s[j * 4 + 0] = __fdividef(ee.x, s.x);
    att_s[j * 4 + 1] = __fdividef(ee.y, s.y);
    att_s[j * 4 + 2] = __fdividef(ee.z, s.z);
    att_s[j * 4 + 3] = __fdividef(ee.w, s.w);
    __syncthreads();

    // ---- phase 3: h_e = sum_j h_e_att ----
    const int fcol = tid >> 2;
    const int hd   = tid & 3;
    {
        float hs = 0.f;
        for (int jj = 0; jj < NN; jj++)
            hs += he[jj * 65 + fcol] * att_s[jj * 4 + hd];
        he_e[tid] = hs;
    }
    __syncthreads();   // phase-1 union data dead; safe to overwrite

    // ---- phase 4: coeff = tanh(h_e_att @ Wx), reduced over j ----
    for (int idx = tid; idx < 128 * 256 / 4; idx += 256)
        ((float4*)wxlo)[idx] = ((const float4*)Wx)[idx];
    __syncthreads();

    float cax = 0.f, cay = 0.f, caz = 0.f;
    const float* wxhi = Wx + 128 * 256;

    for (int j0 = 0; j0 < NN; j0 += 16) {
        // build he_att^T tile: heT[c][jj], stride 20
        #pragma unroll
        for (int jj = 0; jj < 16; jj++)
            heT[tid * 20 + jj] = he[(j0 + jj) * 65 + fcol] * att_s[(j0 + jj) * 4 + hd];
        __syncthreads();

        unsigned long long a2[8];
        #pragma unroll
        for (int q = 0; q < 8; q++) a2[q] = 0ull;

        #pragma unroll 4
        for (int c = 0; c < 128; c++) {
            float w = wxlo[c * 256 + tid];
            unsigned long long w2 = bcast2(w);
            const unsigned long long* hp = (const unsigned long long*)(heT + c * 20);
            #pragma unroll
            for (int q = 0; q < 8; q++) fma2(a2[q], hp[q], w2);
        }
        #pragma unroll 8
        for (int c = 0; c < 128; c++) {
            float w = __ldg(&wxhi[c * 256 + tid]);
            unsigned long long w2 = bcast2(w);
            const unsigned long long* hp = (const unsigned long long*)(heT + (128 + c) * 20);
            #pragma unroll
            for (int q = 0; q < 8; q++) fma2(a2[q], hp[q], w2);
        }

        #pragma unroll
        for (int q = 0; q < 8; q++) {
            float r0, r1;
            unpack2(a2[q], r0, r1);
            float c0 = fast_tanhf(r0);
            float c1 = fast_tanhf(r1);
            float4 x0 = *(const float4*)&xdn[(j0 + 2 * q + 0) * 4];
            float4 x1 = *(const float4*)&xdn[(j0 + 2 * q + 1) * 4];
            cax += x0.x * c0 + x1.x * c1;
            cay += x0.y * c0 + x1.y * c1;
            caz += x0.z * c0 + x1.z * c1;
        }
        __syncthreads();
    }

    // ---- phase 5: comb_sum, comb_norm, delta_v ----
    float* cn     = sm + O_CN;
    float* p1_s   = sm + O_P1;
    float* hcomb  = sm + O_HCOMB;
    float* n1_s   = sm + O_N1;
    float* hn_s   = sm + O_HN;

    const float invN = 1.f / 256.f;
    float csx = cax * invN, csy = cay * invN, csz = caz * invN;
    cn[tid] = csx * csx + csy * csy + csz * csz;
    float wv = Wv_mix[tid];
    float4 dv4 = block_red4<0>(make_float4(wv * csx, wv * csy, wv * csz, 0.f), tid, red);
    __syncthreads();

    // ---- phase 6: tail MLPs ----
    if (tid < 64) {
        float a = bp1[tid];
        for (int c = 0; c < CC; c++) a += cn[c] * Wp1[c * 64 + tid];
        p1_s[tid] = siluf(a);
    }
    __syncthreads();
    if (tid < 64) {
        float a = bp2[tid];
        for (int f = 0; f < 64; f++) a += p1_s[f] * Wp2[f * 64 + tid];
        hcomb[tid] = siluf(a);
    }
    __syncthreads();
    if (tid < 64) {
        float a = bn1[tid];
        for (int f = 0; f < 64; f++)  a += hi_s[f] * Wn1[f * 64 + tid];
        for (int c = 0; c < CC; c++)  a += he_e[c] * Wn1[(64 + c) * 64 + tid];
        for (int f = 0; f < 64; f++)  a += hcomb[f] * Wn1[(320 + f) * 64 + tid];
        n1_s[tid] = siluf(a);
    }
    __syncthreads();
    if (tid < 64) {
        float a = bn2[tid];
        for (int f = 0; f < 64; f++) a += n1_s[f] * Wn2[f * 64 + tid];
        float hv = hi_s[tid] + siluf(a);
        hn_s[tid] = hv;
        outH[nodeI * 64 + tid] = hv;
    }
    __syncthreads();
    float vl = 0.f;
    if (tid < 64) {
        float a = bvel1[tid];
        for (int f = 0; f < 64; f++) a += hn_s[f] * Wvel1[f * 64 + tid];
        vl = siluf(a) * Wvel2[tid];
    }
    float4 vs = block_red4<0>(make_float4(vl, 0.f, 0.f, 0.f), tid, red);
    if (tid == 0) {
        float scale = 2.f * sigmoidf_(vs.x);
        float dvv[3] = {dv4.x, dv4.y, dv4.z};
        #pragma unroll
        for (int t = 0; t < 3; t++) {
            float vn = dvv[t] + scale * v[nodeI * 3 + t];
            outV[nodeI * 3 + t] = vn;
            outX[nodeI * 3 + t] = x[nodeI * 3 + t] + vn;
        }
    }
}

// ---------------- launch ----------------
extern "C" void kernel_launch(void* const* d_in, const int* in_sizes, int n_in,
                              void* d_out, int out_size) {
    const float* h      = (const float*)d_in[0];
    const float* x      = (const float*)d_in[1];
    const float* v      = (const float*)d_in[2];
    const float* means  = (const float*)d_in[3];
    const float* betas  = (const float*)d_in[4];
    const float* W_in   = (const float*)d_in[5];
    const float* b_in   = (const float*)d_in[6];
    const float* W_o1   = (const float*)d_in[7];
    const float* b_o1   = (const float*)d_in[8];
    const float* W_o2   = (const float*)d_in[9];
    const float* b_o2   = (const float*)d_in[10];
    const float* Ws     = (const float*)d_in[11];
    const float* bs     = (const float*)d_in[12];
    const float* lgam   = (const float*)d_in[13];
    const float* Wx     = (const float*)d_in[14];
    const float* Wp1    = (const float*)d_in[15];
    const float* bp1    = (const float*)d_in[16];
    const float* Wp2    = (const float*)d_in[17];
    const float* bp2    = (const float*)d_in[18];
    const float* Wn1    = (const float*)d_in[19];
    const float* bn1    = (const float*)d_in[20];
    const float* Wn2    = (const float*)d_in[21];
    const float* bn2    = (const float*)d_in[22];
    const float* Wv_mix = (const float*)d_in[23];
    const float* Wvel1  = (const float*)d_in[24];
    const float* bvel1  = (const float*)d_in[25];
    const float* Wvel2  = (const float*)d_in[26];

    float* out  = (float*)d_out;
    float* outH = out;                       // [B,N,F]
    float* outX = out + BB * NN * FF;        // [B,N,3]
    float* outV = outX + BB * NN * 3;        // [B,N,3]

    cudaFuncSetAttribute(sake_kernel, cudaFuncAttributeMaxDynamicSharedMemorySize,
                         SMEM_BYTES);

    prenode_kernel<<<BB * NN, 128>>>(h, W_in, W_o1);
    sake_kernel<<<BB * NN, 256, SMEM_BYTES>>>(
        h, x, v, means, betas, b_in, W_o1, b_o1, W_o2, b_o2,
        Ws, bs, lgam, Wx, Wp1, bp1, Wp2, bp2,
        Wn1, bn1, Wn2, bn2, Wv_mix, Wvel1, bvel1, Wvel2,
        outH, outX, outV);
}

// round 4
// speedup vs baseline: 1.2255x; 1.2255x over previous
#include <cuda_runtime.h>
#include <cstdint>

#define BB 2
#define NN 256
#define FF 64
#define HH 64
#define KK 50
#define CC 256

// ---------------- device scratch ----------------
__device__ float g_A [BB*NN*KK];
__device__ float g_Bb[BB*NN*KK];
__device__ float g_U [BB*NN*HH];
__device__ float g_Wp[BB*NN*HH];

// ---------------- helpers ----------------
__device__ __forceinline__ uint32_t smem_u32(const void* p) {
    uint32_t a;
    asm("{ .reg .u64 t; cvta.to.shared.u64 t, %1; cvt.u32.u64 %0, t; }" : "=r"(a) : "l"(p));
    return a;
}
__device__ __forceinline__ float siluf(float a) { return a * __fdividef(1.f, 1.f + __expf(-a)); }
__device__ __forceinline__ float sigm(float a)  { return __fdividef(1.f, 1.f + __expf(-a)); }
__device__ __forceinline__ float ftanh(float x) {
    float e = __expf(-2.f * fabsf(x));
    return copysignf(__fdividef(1.f - e, 1.f + e), x);
}
__device__ __forceinline__ void fma2(unsigned long long& acc, unsigned long long a,
                                     unsigned long long b) {
    asm("fma.rn.f32x2 %0, %1, %2, %0;" : "+l"(acc) : "l"(a), "l"(b));
}
__device__ __forceinline__ unsigned long long bcast2(float w) {
    unsigned long long r;
    asm("mov.b64 %0, {%1, %1};" : "=l"(r) : "f"(w));
    return r;
}
__device__ __forceinline__ unsigned long long pack2(float a, float b) {
    unsigned long long r;
    asm("mov.b64 %0, {%1, %2};" : "=l"(r) : "f"(a), "f"(b));
    return r;
}
__device__ __forceinline__ void unpack2(unsigned long long v, float& x, float& y) {
    asm("mov.b64 {%0, %1}, %2;" : "=f"(x), "=f"(y) : "l"(v));
}
__device__ __forceinline__ void cp16(uint32_t dst, const void* src) {
    asm volatile("cp.async.cg.shared.global [%0], [%1], 16;" :: "r"(dst), "l"(src) : "memory");
}
#define CP_COMMIT() asm volatile("cp.async.commit_group;" ::: "memory")
#define CP_WAIT1()  asm volatile("cp.async.wait_group 1;" ::: "memory")

template<int DO_MAX>
__device__ __forceinline__ float4 block_red4(float4 v, int tid, float* red) {
    #pragma unroll
    for (int o = 16; o > 0; o >>= 1) {
        float ax = __shfl_xor_sync(~0u, v.x, o), ay = __shfl_xor_sync(~0u, v.y, o);
        float az = __shfl_xor_sync(~0u, v.z, o), aw = __shfl_xor_sync(~0u, v.w, o);
        if (DO_MAX) { v.x = fmaxf(v.x, ax); v.y = fmaxf(v.y, ay); v.z = fmaxf(v.z, az); v.w = fmaxf(v.w, aw); }
        else        { v.x += ax; v.y += ay; v.z += az; v.w += aw; }
    }
    if ((tid & 31) == 0) ((float4*)red)[tid >> 5] = v;
    __syncthreads();
    if (tid < 32) {
        float4 r;
        if (tid < 8) r = ((float4*)red)[tid];
        else { float id = DO_MAX ? __int_as_float(0xff800000) : 0.f; r = make_float4(id, id, id, id); }
        #pragma unroll
        for (int o = 4; o > 0; o >>= 1) {
            float ax = __shfl_xor_sync(~0u, r.x, o), ay = __shfl_xor_sync(~0u, r.y, o);
            float az = __shfl_xor_sync(~0u, r.z, o), aw = __shfl_xor_sync(~0u, r.w, o);
            if (DO_MAX) { r.x = fmaxf(r.x, ax); r.y = fmaxf(r.y, ay); r.z = fmaxf(r.z, az); r.w = fmaxf(r.w, aw); }
            else        { r.x += ax; r.y += ay; r.z += az; r.w += aw; }
        }
        if (tid == 0) ((float4*)red)[8] = r;
    }
    __syncthreads();
    float4 out = ((float4*)red)[8];
    __syncthreads();
    return out;
}

// ---------------- K0: per-node precompute ----------------
__global__ void prenode_kernel(const float* __restrict__ h,
                               const float* __restrict__ W_in,
                               const float* __restrict__ W_o1) {
    __shared__ float hs[FF];
    int node = blockIdx.x, t = threadIdx.x;
    if (t < FF) hs[t] = h[node * FF + t];
    __syncthreads();
    if (t < KK) {
        float a = 0.f, bv = 0.f;
        #pragma unroll
        for (int f = 0; f < FF; f++) { float hv = hs[f]; a += hv * W_in[f*KK+t]; bv += hv * W_in[(FF+f)*KK+t]; }
        g_A[node*KK+t] = a; g_Bb[node*KK+t] = bv;
    } else if (t >= 64 && t < 128) {
        int c = t - 64;
        float u = 0.f, w = 0.f;
        #pragma unroll
        for (int f = 0; f < FF; f++) { float hv = hs[f]; u += hv * W_o1[f*HH+c]; w += hv * W_o1[(FF+f)*HH+c]; }
        g_U[node*HH+c] = u; g_Wp[node*HH+c] = w;
    }
}

// ---------------- smem layout (float offsets) ----------------
#define O_HE     0        // 256*65 = 16640
#define O_ATT    16640    // 1024
#define O_XDN    17664    // 1024
#define O_HET    18688    // 256*20 = 5120 (per-pass he_att^T tile)
// aliases inside O_HET region after phase 4:
#define O_CMX    18688    // 256 (written once at end of phase 4)
#define O_CMY    18944
#define O_CMZ    19200
#define O_CN     19456    // 256
#define O_P1     19712    // 64
#define O_HCOMB  19776
#define O_N1     19840
#define O_HN     19904
#define O_HESUM  23808    // 256
#define O_HI     24064
#define O_WIB    24128
#define O_WON    24192
#define O_BO2    24256
#define O_BI     24320
#define O_MEAN   24384
#define O_BETA   24448
#define O_WS     24512    // 256
#define O_BSG    24768    // 8
#define O_XI     24776    // 4
#define O_RED    24784    // 40
#define O_UNION  24832
// phase-1 view of union:
#define O_AS     24832    // 256*51 = 13056
#define O_WO1K   37888    // 50*64 = 3200
#define O_WO2    41088    // 64*64 = 4096
// phase-4 view of union: 2 chunk buffers [64c x 256n] each
#define O_WCH    24832    // 2*16384 = 32768
#define SMEM_FLOATS 57600
#define SMEM_BYTES  (SMEM_FLOATS*4)   // 230400

// ---------------- K1: fused per-(b,i) kernel ----------------
__global__ __launch_bounds__(256, 1)
void sake_kernel(const float* __restrict__ h, const float* __restrict__ x,
                 const float* __restrict__ v,
                 const float* __restrict__ means, const float* __restrict__ betas,
                 const float* __restrict__ b_in,
                 const float* __restrict__ W_o1, const float* __restrict__ b_o1,
                 const float* __restrict__ W_o2, const float* __restrict__ b_o2,
                 const float* __restrict__ Ws,  const float* __restrict__ bs,
                 const float* __restrict__ log_gamma,
                 const float* __restrict__ Wx,
                 const float* __restrict__ Wp1, const float* __restrict__ bp1,
                 const float* __restrict__ Wp2, const float* __restrict__ bp2,
                 const float* __restrict__ Wn1, const float* __restrict__ bn1,
                 const float* __restrict__ Wn2, const float* __restrict__ bn2,
                 const float* __restrict__ Wv_mix,
                 const float* __restrict__ Wvel1, const float* __restrict__ bvel1,
                 const float* __restrict__ Wvel2,
                 float* __restrict__ outH, float* __restrict__ outX,
                 float* __restrict__ outV) {
    extern __shared__ float sm[];
    const int tid = threadIdx.x, wid = tid >> 5, lane = tid & 31;
    const int bid = blockIdx.x, b = bid >> 8, i = bid & 255, nodeI = bid;

    float* he    = sm + O_HE;
    float* att_s = sm + O_ATT;
    float* xdn   = sm + O_XDN;
    float* heT   = sm + O_HET;
    float* he_e  = sm + O_HESUM;
    float* hi_s  = sm + O_HI;
    float* wib   = sm + O_WIB;
    float* won   = sm + O_WON;
    float* bo2_s = sm + O_BO2;
    float* bi_s  = sm + O_BI;
    float* mn_s  = sm + O_MEAN;
    float* bt_s  = sm + O_BETA;
    float* ws_s  = sm + O_WS;
    float* bsg   = sm + O_BSG;
    float* xi_s  = sm + O_XI;
    float* red   = sm + O_RED;
    float* As    = sm + O_AS;
    float* wo1k  = sm + O_WO1K;
    float* wo2   = sm + O_WO2;

    const uint32_t smb = smem_u32(sm);

    // ---- preload ----
    if (tid < FF) {
        hi_s[tid]  = h[nodeI*FF+tid];
        wib[tid]   = g_Wp[nodeI*HH+tid] + b_o1[tid];
        won[tid]   = W_o1[178*HH+tid];
        bo2_s[tid] = b_o2[tid];
    }
    if (tid < KK) {
        bi_s[tid] = g_Bb[nodeI*KK+tid] + b_in[tid];
        mn_s[tid] = means[tid];
        bt_s[tid] = betas[tid];
    }
    ws_s[tid] = Ws[tid];
    if (tid < 4) {
        bsg[tid]   = bs[tid];
        bsg[4+tid] = __expf(log_gamma[tid]);
        if (tid < 3) xi_s[tid] = x[nodeI*3+tid];
    }
    for (int idx = tid; idx < NN*KK; idx += 256) {
        int j2 = idx / KK, k = idx - j2*KK;
        As[j2*51+k] = g_A[b*NN*KK + idx];
    }
    for (int idx = tid; idx < NN*HH; idx += 256) {
        int j2 = idx >> 6, f = idx & 63;
        he[j2*65+f] = g_U[b*NN*HH + idx];
    }
    for (int idx = tid; idx < KK*HH; idx += 256) wo1k[idx] = W_o1[128*HH + idx];
    for (int idx = tid; idx < HH*HH; idx += 256) wo2[idx]  = W_o2[idx];
    __syncthreads();

    // ---- phase 1: edge model (thread = j), f32x2 ----
    const int j = tid;
    float xjx = x[(b*NN+j)*3+0], xjy = x[(b*NN+j)*3+1], xjz = x[(b*NN+j)*3+2];
    float dx = xjx - xi_s[0], dy = xjy - xi_s[1], dz = xjz - xi_s[2];
    float d2 = fmaxf(dx*dx + dy*dy + dz*dz, 0.f);
    float normv = sqrtf(d2 + 1e-5f);
    float rinv  = __fdividef(1.f, normv + 1e-5f);
    *(float4*)&xdn[j*4] = make_float4(dx*rinv, dy*rinv, dz*rinv, normv);
    float en = __expf(-normv);

    {
        float accf[64];
        #pragma unroll
        for (int f = 0; f < 64; f++) accf[f] = he[j*65+f] + wib[f] + normv*won[f];
        unsigned long long acc2[32];
        #pragma unroll
        for (int f2 = 0; f2 < 32; f2++) acc2[f2] = pack2(accf[2*f2], accf[2*f2+1]);

        #pragma unroll 2
        for (int k = 0; k < KK; k++) {
            float hk = As[j*51+k] + bi_s[k];
            float df = en - mn_s[k];
            float s  = __expf(-bt_s[k]*df*df) * hk;
            unsigned long long s2 = bcast2(s);
            const ulonglong2* wr = (const ulonglong2*)&wo1k[k*64];
            #pragma unroll
            for (int f4 = 0; f4 < 16; f4++) {
                ulonglong2 wv = wr[f4];
                fma2(acc2[2*f4],   wv.x, s2);
                fma2(acc2[2*f4+1], wv.y, s2);
            }
        }
        #pragma unroll
        for (int f2 = 0; f2 < 32; f2++) {
            float a0, a1; unpack2(acc2[f2], a0, a1);
            accf[2*f2] = siluf(a0); accf[2*f2+1] = siluf(a1);
        }

        #pragma unroll
        for (int g = 0; g < 4; g++) {
            unsigned long long o2[8];
            const ulonglong2* bo = (const ulonglong2*)&bo2_s[g*16];
            #pragma unroll
            for (int q = 0; q < 4; q++) { ulonglong2 bv = bo[q]; o2[2*q] = bv.x; o2[2*q+1] = bv.y; }
            #pragma unroll 8
            for (int f = 0; f < 64; f++) {
                unsigned long long ab = bcast2(accf[f]);
                const ulonglong2* wr = (const ulonglong2*)&wo2[f*64 + g*16];
                #pragma unroll
                for (int q = 0; q < 4; q++) {
                    ulonglong2 wv = wr[q];
                    fma2(o2[2*q],   wv.x, ab);
                    fma2(o2[2*q+1], wv.y, ab);
                }
            }
            #pragma unroll
            for (int q = 0; q < 8; q++) {
                float r0, r1; unpack2(o2[q], r0, r1);
                he[j*65 + g*16 + 2*q]     = r0;
                he[j*65 + g*16 + 2*q + 1] = r1;
            }
        }
    }

    // ---- phase 2: attentions (softmax over j) ----
    float z0 = bsg[0], z1 = bsg[1], z2 = bsg[2], z3 = bsg[3];
    for (int f = 0; f < 64; f++) {
        float a = he[j*65+f];
        z0 += a*ws_s[f*4+0]; z1 += a*ws_s[f*4+1]; z2 += a*ws_s[f*4+2]; z3 += a*ws_s[f*4+3];
    }
    z0 = (z0 > 0.f) ? z0 : 2.f*(__expf(0.5f*z0) - 1.f);
    z1 = (z1 > 0.f) ? z1 : 2.f*(__expf(0.5f*z1) - 1.f);
    z2 = (z2 > 0.f) ? z2 : 2.f*(__expf(0.5f*z2) - 1.f);
    z3 = (z3 > 0.f) ? z3 : 2.f*(__expf(0.5f*z3) - 1.f);
    float diag = (j == i) ? 1e5f : 0.f;
    float4 el = make_float4(-(normv+diag)*bsg[4], -(normv+diag)*bsg[5],
                            -(normv+diag)*bsg[6], -(normv+diag)*bsg[7]);
    float4 sl = make_float4(z0-diag, z1-diag, z2-diag, z3-diag);

    float4 m  = block_red4<1>(el, tid, red);
    float4 ee = make_float4(__expf(el.x-m.x), __expf(el.y-m.y), __expf(el.z-m.z), __expf(el.w-m.w));
    float4 s  = block_red4<0>(ee, tid, red);
    float4 eucl = make_float4(__fdividef(ee.x,s.x), __fdividef(ee.y,s.y),
                              __fdividef(ee.z,s.z), __fdividef(ee.w,s.w));
    m  = block_red4<1>(sl, tid, red);
    ee = make_float4(__expf(sl.x-m.x), __expf(sl.y-m.y), __expf(sl.z-m.z), __expf(sl.w-m.w));
    s  = block_red4<0>(ee, tid, red);
    float4 sem = make_float4(__fdividef(ee.x,s.x), __fdividef(ee.y,s.y),
                             __fdividef(ee.z,s.z), __fdividef(ee.w,s.w));
    float4 q4 = make_float4(eucl.x*sem.x, eucl.y*sem.y, eucl.z*sem.z, eucl.w*sem.w);
    m  = block_red4<1>(q4, tid, red);
    ee = make_float4(__expf(q4.x-m.x), __expf(q4.y-m.y), __expf(q4.z-m.z), __expf(q4.w-m.w));
    s  = block_red4<0>(ee, tid, red);
    att_s[j*4+0] = __fdividef(ee.x, s.x);
    att_s[j*4+1] = __fdividef(ee.y, s.y);
    att_s[j*4+2] = __fdividef(ee.z, s.z);
    att_s[j*4+3] = __fdividef(ee.w, s.w);
    __syncthreads();

    // ---- phase 3: h_e = sum_j he_att ----
    {
        const int fcol = tid >> 2, hd = tid & 3;
        float hs = 0.f;
        for (int jj = 0; jj < NN; jj++) hs += he[jj*65+fcol] * att_s[jj*4+hd];
        he_e[tid] = hs;
    }
    __syncthreads();   // phase-1 union dead (As/wo1k/wo2) -> chunk buffers

    // ---- phase 4: coeff = tanh(he_att @ Wx), reduced over j ----
    // warp covers n-slice [wid*32, wid*32+32); lane: jp = lane>>3 (4 j's), ng = lane&7 (4 n's)
    {
        const int jp = lane >> 3;
        const int nb = wid*32 + (lane & 7)*4;
        const int fme = tid >> 2, hme = tid & 3;
        float cmxr[4] = {0,0,0,0}, cmyr[4] = {0,0,0,0}, cmzr[4] = {0,0,0,0};

        // prologue: stage chunk 0 -> buf 0
        {
            uint32_t dst = smb + (uint32_t)O_WCH*4u + (uint32_t)tid*16u;
            const float* src = Wx + tid*4;
            #pragma unroll
            for (int r = 0; r < 16; r++) cp16(dst + r*4096u, src + r*1024);
            CP_COMMIT();
        }

        for (int pass = 0; pass < 16; pass++) {
            const int j0 = pass*16;
            __syncthreads();   // protect heT from previous pass readers
            #pragma unroll
            for (int jj = 0; jj < 16; jj++)
                heT[tid*20 + jj] = he[(j0+jj)*65 + fme] * att_s[(j0+jj)*4 + hme];

            unsigned long long acc[4][2];
            #pragma unroll
            for (int q = 0; q < 4; q++) { acc[q][0] = 0ull; acc[q][1] = 0ull; }

            for (int t = 0; t < 4; t++) {
                // prefetch chunk t+1 (mod 4) into buffer (t+1)&1
                {
                    int nc = (t+1) & 3;
                    uint32_t dst = smb + (uint32_t)(O_WCH + ((t+1)&1)*16384)*4u + (uint32_t)tid*16u;
                    const float* src = Wx + nc*16384 + tid*4;
                    #pragma unroll
                    for (int r = 0; r < 16; r++) cp16(dst + r*4096u, src + r*1024);
                    CP_COMMIT();
                }
                CP_WAIT1();
                __syncthreads();   // buf[t&1] + heT ready for all warps

                const float* wb = sm + O_WCH + (t&1)*16384;
                const int cb = t*64;
                #pragma unroll 4
                for (int cc = 0; cc < 64; cc++) {
                    float4 a4 = *(const float4*)&heT[(cb+cc)*20 + jp*4];
                    float4 w4 = *(const float4*)&wb[cc*256 + nb];
                    unsigned long long w01 = pack2(w4.x, w4.y);
                    unsigned long long w23 = pack2(w4.z, w4.w);
                    unsigned long long ab;
                    ab = bcast2(a4.x); fma2(acc[0][0], w01, ab); fma2(acc[0][1], w23, ab);
                    ab = bcast2(a4.y); fma2(acc[1][0], w01, ab); fma2(acc[1][1], w23, ab);
                    ab = bcast2(a4.z); fma2(acc[2][0], w01, ab); fma2(acc[2][1], w23, ab);
                    ab = bcast2(a4.w); fma2(acc[3][0], w01, ab); fma2(acc[3][1], w23, ab);
                }
            }

            // epilogue: tanh + xd-weighted accumulate (registers only)
            #pragma unroll
            for (int q = 0; q < 4; q++) {
                float c0, c1, c2, c3;
                unpack2(acc[q][0], c0, c1);
                unpack2(acc[q][1], c2, c3);
                float4 xd4 = *(const float4*)&xdn[(j0 + jp*4 + q)*4];
                float t0 = ftanh(c0), t1 = ftanh(c1), t2 = ftanh(c2), t3 = ftanh(c3);
                cmxr[0] += xd4.x*t0; cmyr[0] += xd4.y*t0; cmzr[0] += xd4.z*t0;
                cmxr[1] += xd4.x*t1; cmyr[1] += xd4.y*t1; cmzr[1] += xd4.z*t1;
                cmxr[2] += xd4.x*t2; cmyr[2] += xd4.y*t2; cmzr[2] += xd4.z*t2;
                cmxr[3] += xd4.x*t3; cmyr[3] += xd4.y*t3; cmzr[3] += xd4.z*t3;
            }
        }
        __syncthreads();   // all passes done; heT region reusable as cm arrays

        // reduce over jp groups (lane bits 3,4), then store (warp-exclusive n ranges)
        #pragma unroll
        for (int p = 0; p < 4; p++) {
            #pragma unroll
            for (int o = 8; o <= 16; o <<= 1) {
                cmxr[p] += __shfl_xor_sync(~0u, cmxr[p], o);
                cmyr[p] += __shfl_xor_sync(~0u, cmyr[p], o);
                cmzr[p] += __shfl_xor_sync(~0u, cmzr[p], o);
            }
        }
        if (jp == 0) {
            #pragma unroll
            for (int p = 0; p < 4; p++) {
                sm[O_CMX + nb + p] = cmxr[p];
                sm[O_CMY + nb + p] = cmyr[p];
                sm[O_CMZ + nb + p] = cmzr[p];
            }
        }
    }
    __syncthreads();

    // ---- phase 5: comb_sum / comb_norm / delta_v ----
    float* cn    = sm + O_CN;
    float* p1_s  = sm + O_P1;
    float* hcomb = sm + O_HCOMB;
    float* n1_s  = sm + O_N1;
    float* hn_s  = sm + O_HN;
    const float invN = 1.f/256.f;
    float csx = sm[O_CMX + tid]*invN, csy = sm[O_CMY + tid]*invN, csz = sm[O_CMZ + tid]*invN;
    cn[tid] = csx*csx + csy*csy + csz*csz;
    float wv = Wv_mix[tid];
    float4 dv4 = block_red4<0>(make_float4(wv*csx, wv*csy, wv*csz, 0.f), tid, red);

    // ---- phase 6: tail MLPs ----
    if (tid < 64) {
        float a = bp1[tid];
        for (int c = 0; c < CC; c++) a += cn[c] * Wp1[c*64+tid];
        p1_s[tid] = siluf(a);
    }
    __syncthreads();
    if (tid < 64) {
        float a = bp2[tid];
        for (int f = 0; f < 64; f++) a += p1_s[f] * Wp2[f*64+tid];
        hcomb[tid] = siluf(a);
    }
    __syncthreads();
    if (tid < 64) {
        float a = bn1[tid];
        for (int f = 0; f < 64; f++) a += hi_s[f]  * Wn1[f*64+tid];
        for (int c = 0; c < CC; c++) a += he_e[c]  * Wn1[(64+c)*64+tid];
        for (int f = 0; f < 64; f++) a += hcomb[f] * Wn1[(320+f)*64+tid];
        n1_s[tid] = siluf(a);
    }
    __syncthreads();
    if (tid < 64) {
        float a = bn2[tid];
        for (int f = 0; f < 64; f++) a += n1_s[f] * Wn2[f*64+tid];
        float hv = hi_s[tid] + siluf(a);
        hn_s[tid] = hv;
        outH[nodeI*64+tid] = hv;
    }
    __syncthreads();
    float vl = 0.f;
    if (tid < 64) {
        float a = bvel1[tid];
        for (int f = 0; f < 64; f++) a += hn_s[f] * Wvel1[f*64+tid];
        vl = siluf(a) * Wvel2[tid];
    }
    float4 vs = block_red4<0>(make_float4(vl, 0.f, 0.f, 0.f), tid, red);
    if (tid == 0) {
        float scale = 2.f * sigm(vs.x);
        float dvv[3] = {dv4.x, dv4.y, dv4.z};
        #pragma unroll
        for (int t = 0; t < 3; t++) {
            float vn = dvv[t] + scale * v[nodeI*3+t];
            outV[nodeI*3+t] = vn;
            outX[nodeI*3+t] = x[nodeI*3+t] + vn;
        }
    }
}

// ---------------- launch ----------------
extern "C" void kernel_launch(void* const* d_in, const int* in_sizes, int n_in,
                              void* d_out, int out_size) {
    const float* h      = (const float*)d_in[0];
    const float* x      = (const float*)d_in[1];
    const float* v      = (const float*)d_in[2];
    const float* means  = (const float*)d_in[3];
    const float* betas  = (const float*)d_in[4];
    const float* W_in   = (const float*)d_in[5];
    const float* b_in   = (const float*)d_in[6];
    const float* W_o1   = (const float*)d_in[7];
    const float* b_o1   = (const float*)d_in[8];
    const float* W_o2   = (const float*)d_in[9];
    const float* b_o2   = (const float*)d_in[10];
    const float* Ws     = (const float*)d_in[11];
    const float* bs     = (const float*)d_in[12];
    const float* lgam   = (const float*)d_in[13];
    const float* Wx     = (const float*)d_in[14];
    const float* Wp1    = (const float*)d_in[15];
    const float* bp1    = (const float*)d_in[16];
    const float* Wp2    = (const float*)d_in[17];
    const float* bp2    = (const float*)d_in[18];
    const float* Wn1    = (const float*)d_in[19];
    const float* bn1    = (const float*)d_in[20];
    const float* Wn2    = (const float*)d_in[21];
    const float* bn2    = (const float*)d_in[22];
    const float* Wv_mix = (const float*)d_in[23];
    const float* Wvel1  = (const float*)d_in[24];
    const float* bvel1  = (const float*)d_in[25];
    const float* Wvel2  = (const float*)d_in[26];

    float* out  = (float*)d_out;
    float* outH = out;
    float* outX = out + BB*NN*FF;
    float* outV = outX + BB*NN*3;

    cudaFuncSetAttribute(sake_kernel, cudaFuncAttributeMaxDynamicSharedMemorySize, SMEM_BYTES);

    prenode_kernel<<<BB*NN, 128>>>(h, W_in, W_o1);
    sake_kernel<<<BB*NN, 256, SMEM_BYTES>>>(
        h, x, v, means, betas, b_in, W_o1, b_o1, W_o2, b_o2,
        Ws, bs, lgam, Wx, Wp1, bp1, Wp2, bp2,
        Wn1, bn1, Wn2, bn2, Wv_mix, Wvel1, bvel1, Wvel2,
        outH, outX, outV);
}